// round 15
// baseline (speedup 1.0000x reference)
#include <cuda_runtime.h>
#include <cuda_fp16.h>

#define B_ 4
#define H_ 56
#define W_ 56
#define HW_ (H_*W_)

typedef unsigned int  u32;
typedef unsigned short u16;

// ---------------------------------------------------------------------------
// Scratch (device globals; no allocation allowed)
// ---------------------------------------------------------------------------
__device__ __align__(16) float g_xT   [B_*HW_*64];
__device__ __align__(16) __half g_xh [B_*HW_*64];
__device__ __align__(16) float g_off1 [B_*HW_*50];
__device__ __align__(16) float g_attn1[B_*HW_*64];
__device__ __align__(16) __half g_a1h[B_*HW_*64];
__device__ __align__(16) float g_off2 [B_*HW_*98];
// fp16 weights: [tap][co(COP)][ci(64)]
__device__ __align__(16) __half g_w1h[25*64*64];
__device__ __align__(16) __half g_w2h[49*112*64];
__device__ __align__(16) float g_dw1T [25*64];   // [kk][c]
__device__ __align__(16) float g_dw2T [49*64];

// ---------------------------------------------------------------------------
// helpers
// ---------------------------------------------------------------------------
__device__ __forceinline__ void cp16(u32 dst, const void* src){
    asm volatile("cp.async.cg.shared.global [%0], [%1], 16;" :: "r"(dst), "l"(src));
}
#define CP_COMMIT() asm volatile("cp.async.commit_group;")
#define CP_WAIT0()  asm volatile("cp.async.wait_group 0;")
__device__ __forceinline__ void mma_f16(float* d, u32 a0,u32 a1,u32 a2,u32 a3,u32 b0,u32 b1){
    asm volatile("mma.sync.aligned.m16n8k16.row.col.f32.f16.f16.f32 "
      "{%0,%1,%2,%3}, {%4,%5,%6,%7}, {%8,%9}, {%0,%1,%2,%3};"
      : "+f"(d[0]),"+f"(d[1]),"+f"(d[2]),"+f"(d[3])
      : "r"(a0),"r"(a1),"r"(a2),"r"(a3),"r"(b0),"r"(b1));
}

// ---------------------------------------------------------------------------
// Fused prelude: transpose blocks [0, 224) + weight-prep blocks [224, ...)
// ---------------------------------------------------------------------------
#define NPREP_ (25*64*64 + 49*112*64 + 25*64 + 49*64)
#define PREP_BLOCKS ((NPREP_ + 255)/256)

__global__ void __launch_bounds__(256) prelude_kernel(
    const float* __restrict__ x, float* __restrict__ xT, __half* __restrict__ xh,
    const float* __restrict__ ow1, const float* __restrict__ ow2,
    const float* __restrict__ dw1, const float* __restrict__ dw2,
    __half* __restrict__ w1h, __half* __restrict__ w2h,
    float* __restrict__ dw1T, float* __restrict__ dw2T)
{
    const int t = threadIdx.x;
    if (blockIdx.x < 224) {
        int h = blockIdx.x % H_, b = blockIdx.x / H_;
        __shared__ float s[64*W_];
        for (int i = t; i < 64*W_; i += 256) {
            int c = i / W_, w = i - c*W_;
            s[i] = x[((b*64 + c)*H_ + h)*W_ + w];
        }
        __syncthreads();
        size_t rb = (size_t)(b*H_ + h)*W_*64;
        for (int j = t; j < 32*W_; j += 256) {
            int w = j >> 5, cp = j & 31; int c0 = cp*2;
            float f0 = s[c0*W_ + w], f1 = s[(c0+1)*W_ + w];
            xT[rb + w*64 + c0]   = f0;
            xT[rb + w*64 + c0+1] = f1;
            __half2 hp; hp.x = __float2half_rn(f0); hp.y = __float2half_rn(f1);
            *(__half2*)(xh + rb + w*64 + c0) = hp;
        }
        return;
    }
    const int N1 = 25*64*64;
    const int N2 = 49*112*64;
    const int N3 = 25*64;
    const int N4 = 49*64;
    int idx = (blockIdx.x - 224)*256 + t;
    if (idx < N1) {
        int ci = idx & 63; int r = idx >> 6; int co = r & 63; int tap = r >> 6;
        float v = (co < 50) ? ow1[(size_t)(co*64 + ci)*25 + tap] : 0.f;
        w1h[idx] = __float2half_rn(v);
    } else if (idx < N1 + N2) {
        int i = idx - N1;
        int ci = i & 63; int r = i >> 6; int co = r % 112; int tap = r / 112;
        float v = (co < 98) ? ow2[(size_t)(co*64 + ci)*49 + tap] : 0.f;
        w2h[i] = __float2half_rn(v);
    } else if (idx < N1 + N2 + N3) {
        int i = idx - N1 - N2;
        int kk = i >> 6, c = i & 63;
        dw1T[i] = dw1[c*25 + kk];
    } else if (idx < N1 + N2 + N3 + N4) {
        int i = idx - N1 - N2 - N3;
        int kk = i >> 6, c = i & 63;
        dw2T[i] = dw2[c*49 + kk];
    }
}

// ---------------------------------------------------------------------------
// Offset conv, implicit GEMM on tensor cores, single fp16 pass.
// Block = 2 output rows x half the co range; M = 128; 8 warps x 1 m-tile.
// grid = (28, B, 2) = 224 blocks; ~40KB smem -> 2 blocks co-resident per SM
// so barriers/cp-waits in one block are covered by mma issue in the other.
// ---------------------------------------------------------------------------
template<int K, int DIL, int PAD, int CO, int COP>
__global__ void __launch_bounds__(256) conv_mma_kernel(
    const __half* __restrict__ Ih,
    const __half* __restrict__ Wh,
    const float* __restrict__ bias, float* __restrict__ out)
{
    constexpr int KK  = K*K;
    constexpr int WE  = (K-1)*DIL + 64;   // extended row (halo + 64 m-pad)
    constexpr int COH = COP/2;
    constexpr int NTn = COH/8;            // n-tiles of 8 per warp
    constexpr int AE  = WE*72;            // u16 elems per rr plane
    constexpr int BE  = COH*72;           // u16 elems per B buffer

    extern __shared__ __align__(16) u16 sm[];
    u16* sA = sm;                         // 2 planes: rr0, rr1
    u16* sB = sm + 2*AE;                  // [buf] BE each

    const int t = threadIdx.x, lane = t & 31, wid = t >> 5;
    const int h0 = blockIdx.x*2, b = blockIdx.y;
    const int colbase = blockIdx.z * COH;
    const int kq   = (lane & 3)*2;
    const int qrow = lane >> 2;
    const int mt = wid;                   // 0..7 : row = mt>>2, px-tile = mt&3

    const u32 smbase = (u32)__cvta_generic_to_shared(sm);
    const u32 dB = smbase + 2*AE*2;       // bytes

    float acc[NTn][4];
    #pragma unroll
    for (int nt = 0; nt < NTn; ++nt) {
        int co0 = colbase + nt*8 + kq;
        float b0 = (co0   < CO) ? bias[co0]   : 0.f;
        float b1 = (co0+1 < CO) ? bias[co0+1] : 0.f;
        acc[nt][0] = b0; acc[nt][1] = b1;
        acc[nt][2] = b0; acc[nt][3] = b1;
    }

    // prologue: stage B for tap 0 into buffer 0
    for (int c = t; c < COH*8; c += 256) {
        int co = c >> 3, kc = c & 7;
        cp16(dB + (u32)(co*72 + kc*8)*2, Wh + (size_t)(colbase + co)*64 + kc*8);
    }
    CP_COMMIT();

    for (int ky = 0; ky < K; ++ky) {
        const int hp = h0 + ky*DIL - PAD;    // input row for rr=0
        for (int c = t; c < 2*WE*8; c += 256) {
            int rr = c / (WE*8);
            int j  = (c >> 3) % WE;
            int kc = c & 7;
            int g = j - PAD, hh = hp + rr;
            u32 off = (u32)(rr*AE + j*72 + kc*8)*2;
            if ((unsigned)hh < (unsigned)H_ && (unsigned)g < (unsigned)W_) {
                cp16(smbase + off, Ih + ((size_t)(b*H_ + hh)*W_ + g)*64 + kc*8);
            } else {
                float4 z = make_float4(0.f,0.f,0.f,0.f);
                *(float4*)(sA + rr*AE + j*72 + kc*8) = z;
            }
        }
        CP_COMMIT();
        CP_WAIT0();
        __syncthreads();

        for (int kx = 0; kx < K; ++kx) {
            const int tap = ky*K + kx;
            if (tap + 1 < KK) {
                u32 dst = dB + (u32)((tap+1) & 1)*(BE*2);
                const __half* wh = Wh + (size_t)(tap+1)*COP*64;
                for (int c = t; c < COH*8; c += 256) {
                    int co = c >> 3, kc = c & 7;
                    cp16(dst + (u32)(co*72 + kc*8)*2,
                         wh + (size_t)(colbase + co)*64 + kc*8);
                }
                CP_COMMIT();
            }

            const u16* Bh = sB + (size_t)(tap & 1)*BE;
            const u16* A0 = sA + (mt>>2)*AE;
            const int a0 = ((mt & 3)*16 + qrow + kx*DIL)*72;

            #pragma unroll
            for (int ks = 0; ks < 4; ++ks) {
                const int kk = ks*16 + kq;
                u32 xh0 = *(const u32*)(A0 + a0 + kk);
                u32 xh1 = *(const u32*)(A0 + a0 + 8*72 + kk);
                u32 xh2 = *(const u32*)(A0 + a0 + kk + 8);
                u32 xh3 = *(const u32*)(A0 + a0 + 8*72 + kk + 8);
                #pragma unroll
                for (int nt = 0; nt < NTn; ++nt) {
                    const int cb = (nt*8 + qrow)*72;
                    u32 bh0 = *(const u32*)(Bh + cb + kk);
                    u32 bh1 = *(const u32*)(Bh + cb + kk + 8);
                    mma_f16(acc[nt], xh0,xh1,xh2,xh3, bh0,bh1);
                }
            }
            CP_WAIT0();
            __syncthreads();
        }
    }

    // epilogue
    const int row = h0 + (mt >> 2);
    const int px0 = (mt & 3)*16 + qrow;
    const int px1 = px0 + 8;
    float* po = out + (size_t)(b*H_ + row)*W_*CO;
    #pragma unroll
    for (int nt = 0; nt < NTn; ++nt) {
        int co0 = colbase + nt*8 + kq;
        if (px0 < 56) {
            if (co0   < CO) po[px0*CO + co0]   = acc[nt][0];
            if (co0+1 < CO) po[px0*CO + co0+1] = acc[nt][1];
        }
        if (px1 < 56) {
            if (co0   < CO) po[px1*CO + co0]   = acc[nt][2];
            if (co0+1 < CO) po[px1*CO + co0+1] = acc[nt][3];
        }
    }
}

// ---------------------------------------------------------------------------
// Deformable depthwise sampling, stage 1 (emits fp32 + fp16).
// grid = (2 half-rows, H, B), 448 threads; gather unrolled x4.
// ---------------------------------------------------------------------------
template<int K, int DIL, int PAD>
__global__ void __launch_bounds__(448) deform_sample_kernel(
    const float* __restrict__ img, const float* __restrict__ off,
    const float* __restrict__ dwT, float* __restrict__ outp,
    __half* __restrict__ oh)
{
    constexpr int KK = K*K;
    constexpr int NTASK = 28*KK;
    __shared__ __align__(16) float4 s_dw4[KK*16];
    __shared__ __align__(16) short4 s_idx[NTASK];
    __shared__ __align__(16) float4 s_wt [NTASK];

    const int t = threadIdx.x;
    const int half = blockIdx.x, h = blockIdx.y, b = blockIdx.z;
    const int w0 = half * 28;

    const float4* dwT4 = (const float4*)dwT;
    for (int i = t; i < KK*16; i += 448) s_dw4[i] = dwT4[i];

    const float2* ob2 = (const float2*)(off + ((size_t)(b*H_ + h)*W_ + w0)*2*KK);
    for (int i = t; i < NTASK; i += 448) {
        int wl = i / KK, kk = i - wl*KK;
        int ky = kk / K, kx = kk - ky*K;
        float2 d = ob2[i];
        float py = (float)(h + ky*DIL - PAD) + d.x;
        float px = (float)(w0 + wl + kx*DIL - PAD) + d.y;
        float y0f = floorf(py), x0f = floorf(px);
        float wy = py - y0f,    wx = px - x0f;
        int y0 = (int)y0f, x0i = (int)x0f;
        int y1 = y0 + 1,   x1  = x0i + 1;
        float vy0 = (y0  >= 0 && y0  < H_) ? 1.f : 0.f;
        float vy1 = (y1  >= 0 && y1  < H_) ? 1.f : 0.f;
        float vx0 = (x0i >= 0 && x0i < W_) ? 1.f : 0.f;
        float vx1 = (x1  >= 0 && x1  < W_) ? 1.f : 0.f;
        int y0c = min(max(y0, 0), H_-1), y1c = min(max(y1, 0), H_-1);
        int x0c = min(max(x0i,0), W_-1), x1c = min(max(x1, 0), W_-1);
        int r0 = y0c*W_, r1 = y1c*W_;
        s_idx[i] = make_short4((short)(r0+x0c), (short)(r0+x1c),
                               (short)(r1+x0c), (short)(r1+x1c));
        s_wt[i]  = make_float4((1.f-wy)*(1.f-wx)*vy0*vx0,
                               (1.f-wy)*wx      *vy0*vx1,
                               wy      *(1.f-wx)*vy1*vx0,
                               wy      *wx      *vy1*vx1);
    }
    __syncthreads();

    const int c4 = t & 15;
    const int wl = t >> 4;
    const int w  = w0 + wl;
    const float4* imgb = (const float4*)img + (size_t)b*HW_*16;

    float4 a = make_float4(0.f, 0.f, 0.f, 0.f);
    #pragma unroll 4
    for (int kk = 0; kk < KK; ++kk) {
        short4 id = s_idx[wl*KK + kk];
        float4 wt = s_wt [wl*KK + kk];
        float4 g00 = imgb[(int)id.x*16 + c4];
        float4 g01 = imgb[(int)id.y*16 + c4];
        float4 g10 = imgb[(int)id.z*16 + c4];
        float4 g11 = imgb[(int)id.w*16 + c4];
        float4 dv  = s_dw4[kk*16 + c4];
        float sx_ = g00.x*wt.x + g01.x*wt.y + g10.x*wt.z + g11.x*wt.w;
        float sy_ = g00.y*wt.x + g01.y*wt.y + g10.y*wt.z + g11.y*wt.w;
        float sz_ = g00.z*wt.x + g01.z*wt.y + g10.z*wt.z + g11.z*wt.w;
        float sw_ = g00.w*wt.x + g01.w*wt.y + g10.w*wt.z + g11.w*wt.w;
        a.x += sx_*dv.x; a.y += sy_*dv.y; a.z += sz_*dv.z; a.w += sw_*dv.w;
    }
    const size_t p = (size_t)(b*H_ + h)*W_ + w;
    ((float4*)outp)[p*16 + c4] = a;
    __half2 hp0; hp0.x = __float2half_rn(a.x); hp0.y = __float2half_rn(a.y);
    __half2 hp1; hp1.x = __float2half_rn(a.z); hp1.y = __float2half_rn(a.w);
    __half2* ph = (__half2*)(oh + p*64 + c4*4);
    ph[0] = hp0; ph[1] = hp1;
}

// ---------------------------------------------------------------------------
// Stage-2 deform + fused 1x1 pointwise conv + x-multiply (NCHW output).
// ---------------------------------------------------------------------------
template<int K, int DIL, int PAD>
__global__ void __launch_bounds__(448) deform_pw_kernel(
    const float* __restrict__ img,   // attn1 NHWC
    const float* __restrict__ off,   // off2 NHWC
    const float* __restrict__ dwT,   // [kk][c]
    const float* __restrict__ pw,    // [64,64] (co,ci)
    const float* __restrict__ pb,    // [64]
    const float* __restrict__ x,     // original x, NCHW
    float* __restrict__ out)         // NCHW
{
    constexpr int KK = K*K;
    constexpr int NTASK = 28*KK;
    extern __shared__ __align__(16) char sraw[];
    float4* s_dw4 = (float4*)sraw;                               // KK*16*16 B
    char*   reg   = sraw + KK*16*16;
    short4* s_idx = (short4*)reg;                                // NTASK*8
    float4* s_wt  = (float4*)(reg + NTASK*8);                    // NTASK*16
    float*  s_attn= (float*) (reg + NTASK*24);                   // 28*64*4
    // overlay (valid after gather):
    float*  s_pwT = (float*)reg;                                 // 16384
    float*  s_pb  = (float*)(reg + 16384);                       // 256
    float*  s_out = (float*)(reg + 16640);                       // 28*64*4

    const int t = threadIdx.x;
    const int half = blockIdx.x, h = blockIdx.y, b = blockIdx.z;
    const int w0 = half * 28;

    const float4* dwT4 = (const float4*)dwT;
    for (int i = t; i < KK*16; i += 448) s_dw4[i] = dwT4[i];

    const float2* ob2 = (const float2*)(off + ((size_t)(b*H_ + h)*W_ + w0)*2*KK);
    for (int i = t; i < NTASK; i += 448) {
        int wl = i / KK, kk = i - wl*KK;
        int ky = kk / K, kx = kk - ky*K;
        float2 d = ob2[i];
        float py = (float)(h + ky*DIL - PAD) + d.x;
        float px = (float)(w0 + wl + kx*DIL - PAD) + d.y;
        float y0f = floorf(py), x0f = floorf(px);
        float wy = py - y0f,    wx = px - x0f;
        int y0 = (int)y0f, x0i = (int)x0f;
        int y1 = y0 + 1,   x1  = x0i + 1;
        float vy0 = (y0  >= 0 && y0  < H_) ? 1.f : 0.f;
        float vy1 = (y1  >= 0 && y1  < H_) ? 1.f : 0.f;
        float vx0 = (x0i >= 0 && x0i < W_) ? 1.f : 0.f;
        float vx1 = (x1  >= 0 && x1  < W_) ? 1.f : 0.f;
        int y0c = min(max(y0, 0), H_-1), y1c = min(max(y1, 0), H_-1);
        int x0c = min(max(x0i,0), W_-1), x1c = min(max(x1, 0), W_-1);
        int r0 = y0c*W_, r1 = y1c*W_;
        s_idx[i] = make_short4((short)(r0+x0c), (short)(r0+x1c),
                               (short)(r1+x0c), (short)(r1+x1c));
        s_wt[i]  = make_float4((1.f-wy)*(1.f-wx)*vy0*vx0,
                               (1.f-wy)*wx      *vy0*vx1,
                               wy      *(1.f-wx)*vy1*vx0,
                               wy      *wx      *vy1*vx1);
    }
    __syncthreads();

    const int c4 = t & 15;
    const int wl = t >> 4;
    const float4* imgb = (const float4*)img + (size_t)b*HW_*16;

    float4 a = make_float4(0.f, 0.f, 0.f, 0.f);
    #pragma unroll 4
    for (int kk = 0; kk < KK; ++kk) {
        short4 id = s_idx[wl*KK + kk];
        float4 wt = s_wt [wl*KK + kk];
        float4 g00 = imgb[(int)id.x*16 + c4];
        float4 g01 = imgb[(int)id.y*16 + c4];
        float4 g10 = imgb[(int)id.z*16 + c4];
        float4 g11 = imgb[(int)id.w*16 + c4];
        float4 dv  = s_dw4[kk*16 + c4];
        float sx_ = g00.x*wt.x + g01.x*wt.y + g10.x*wt.z + g11.x*wt.w;
        float sy_ = g00.y*wt.x + g01.y*wt.y + g10.y*wt.z + g11.y*wt.w;
        float sz_ = g00.z*wt.x + g01.z*wt.y + g10.z*wt.z + g11.z*wt.w;
        float sw_ = g00.w*wt.x + g01.w*wt.y + g10.w*wt.z + g11.w*wt.w;
        a.x += sx_*dv.x; a.y += sy_*dv.y; a.z += sz_*dv.z; a.w += sw_*dv.w;
    }
    ((float4*)s_attn)[wl*16 + c4] = a;
    __syncthreads();                         // gather done; idx/wt now dead

    for (int i = t; i < 4096; i += 448) {
        int co = i >> 6, ci = i & 63;
        s_pwT[ci*64 + co] = pw[i];
    }
    if (t < 64) s_pb[t] = pb[t];
    __syncthreads();

    const int co0 = c4*4;
    float4 accp = make_float4(0.f, 0.f, 0.f, 0.f);
    const float* ar = s_attn + wl*64;
    #pragma unroll 8
    for (int ci = 0; ci < 64; ++ci) {
        float av = ar[ci];
        float4 wv = ((const float4*)(s_pwT + ci*64))[c4];
        accp.x += av*wv.x; accp.y += av*wv.y;
        accp.z += av*wv.z; accp.w += av*wv.w;
    }
    s_out[(co0  )*28 + wl] = accp.x + s_pb[co0];
    s_out[(co0+1)*28 + wl] = accp.y + s_pb[co0+1];
    s_out[(co0+2)*28 + wl] = accp.z + s_pb[co0+2];
    s_out[(co0+3)*28 + wl] = accp.w + s_pb[co0+3];
    __syncthreads();

    for (int i = t; i < 64*28; i += 448) {
        int c = i / 28, wl2 = i - c*28;
        size_t idx = ((size_t)(b*64 + c)*H_ + h)*W_ + w0 + wl2;
        out[idx] = x[idx] * s_out[c*28 + wl2];
    }
}

// ---------------------------------------------------------------------------
extern "C" void kernel_launch(void* const* d_in, const int* in_sizes, int n_in,
                              void* d_out, int out_size)
{
    const float* x   = (const float*)d_in[0];
    const float* ow1 = (const float*)d_in[1];
    const float* ob1 = (const float*)d_in[2];
    const float* dw1 = (const float*)d_in[3];
    const float* ow2 = (const float*)d_in[4];
    const float* ob2 = (const float*)d_in[5];
    const float* dw2 = (const float*)d_in[6];
    const float* pww = (const float*)d_in[7];
    const float* pwb = (const float*)d_in[8];
    float* out = (float*)d_out;

    float *xT, *off1, *attn1, *off2, *dw1T, *dw2T;
    __half *xh, *a1h, *w1h, *w2h;
    cudaGetSymbolAddress((void**)&xT,    g_xT);
    cudaGetSymbolAddress((void**)&xh,    g_xh);
    cudaGetSymbolAddress((void**)&off1,  g_off1);
    cudaGetSymbolAddress((void**)&attn1, g_attn1);
    cudaGetSymbolAddress((void**)&a1h,   g_a1h);
    cudaGetSymbolAddress((void**)&off2,  g_off2);
    cudaGetSymbolAddress((void**)&w1h,   g_w1h);
    cudaGetSymbolAddress((void**)&w2h,   g_w2h);
    cudaGetSymbolAddress((void**)&dw1T,  g_dw1T);
    cudaGetSymbolAddress((void**)&dw2T,  g_dw2T);

    // conv smem: 2 A planes + 2 B buffers (bytes)
    const int SMEM1 = 2*(68*72)*2 + 2*(32*72)*2;    // 28800
    const int SMEM2 = 2*(82*72)*2 + 2*(56*72)*2;    // 39744
    const int SMEMD = 49*16*16 + 28*49*24 + 28*64*4; // 52640
    cudaFuncSetAttribute(conv_mma_kernel<5,1,2,50,64>,
        cudaFuncAttributeMaxDynamicSharedMemorySize, SMEM1);
    cudaFuncSetAttribute(conv_mma_kernel<7,3,9,98,112>,
        cudaFuncAttributeMaxDynamicSharedMemorySize, SMEM2);
    cudaFuncSetAttribute(deform_pw_kernel<7,3,9>,
        cudaFuncAttributeMaxDynamicSharedMemorySize, SMEMD);

    // fused prelude: 224 transpose blocks + weight-prep blocks
    prelude_kernel<<<224 + PREP_BLOCKS, 256>>>(
        x, xT, xh, ow1, ow2, dw1, dw2, w1h, w2h, dw1T, dw2T);

    // stage 1: K=5, dil=1, pad=2, CO=50 (pad 64)
    conv_mma_kernel<5,1,2,50,64><<<dim3(28, B_, 2), 256, SMEM1>>>(
        xh, w1h, ob1, off1);
    deform_sample_kernel<5,1,2><<<dim3(2, H_, B_), 448>>>(
        xT, off1, dw1T, attn1, a1h);

    // stage 2: K=7, dil=3, pad=9, CO=98 (pad 112)
    conv_mma_kernel<7,3,9,98,112><<<dim3(28, B_, 2), 256, SMEM2>>>(
        a1h, w2h, ob2, off2);

    // deform2 + pointwise + x-multiply, fused
    deform_pw_kernel<7,3,9><<<dim3(2, H_, B_), 448, SMEMD>>>(
        attn1, off2, dw2T, pww, pwb, x, out);
}

// round 16
// speedup vs baseline: 1.1139x; 1.1139x over previous
#include <cuda_runtime.h>
#include <cuda_fp16.h>

#define B_ 4
#define H_ 56
#define W_ 56
#define HW_ (H_*W_)

typedef unsigned int  u32;
typedef unsigned short u16;

// ---------------------------------------------------------------------------
// Scratch (device globals; no allocation allowed)
// ---------------------------------------------------------------------------
__device__ __align__(16) __half g_xh [B_*HW_*64];
__device__ __align__(16) float g_off1 [B_*HW_*50];
__device__ __align__(16) __half g_a1h[B_*HW_*64];
__device__ __align__(16) float g_off2 [B_*HW_*98];
// fp16 weights: [tap][co(COP)][ci(64)]
__device__ __align__(16) __half g_w1h[25*64*64];
__device__ __align__(16) __half g_w2h[49*112*64];
__device__ __align__(16) float g_dw1T [25*64];   // [kk][c]
__device__ __align__(16) float g_dw2T [49*64];

// ---------------------------------------------------------------------------
// helpers
// ---------------------------------------------------------------------------
__device__ __forceinline__ void cp16(u32 dst, const void* src){
    asm volatile("cp.async.cg.shared.global [%0], [%1], 16;" :: "r"(dst), "l"(src));
}
#define CP_COMMIT() asm volatile("cp.async.commit_group;")
#define CP_WAIT0()  asm volatile("cp.async.wait_group 0;")
__device__ __forceinline__ void mma_f16(float* d, u32 a0,u32 a1,u32 a2,u32 a3,u32 b0,u32 b1){
    asm volatile("mma.sync.aligned.m16n8k16.row.col.f32.f16.f16.f32 "
      "{%0,%1,%2,%3}, {%4,%5,%6,%7}, {%8,%9}, {%0,%1,%2,%3};"
      : "+f"(d[0]),"+f"(d[1]),"+f"(d[2]),"+f"(d[3])
      : "r"(a0),"r"(a1),"r"(a2),"r"(a3),"r"(b0),"r"(b1));
}
// load 4 channels stored as fp16 (8 bytes) and widen to float4
__device__ __forceinline__ float4 ld4h(const uint2* p){
    uint2 q = *p;
    __half2 h0 = *reinterpret_cast<__half2*>(&q.x);
    __half2 h1 = *reinterpret_cast<__half2*>(&q.y);
    float2 f0 = __half22float2(h0), f1 = __half22float2(h1);
    return make_float4(f0.x, f0.y, f1.x, f1.y);
}

// ---------------------------------------------------------------------------
// Fused prelude: transpose blocks [0, 224) + weight-prep blocks [224, ...)
// ---------------------------------------------------------------------------
#define NPREP_ (25*64*64 + 49*112*64 + 25*64 + 49*64)
#define PREP_BLOCKS ((NPREP_ + 255)/256)

__global__ void __launch_bounds__(256) prelude_kernel(
    const float* __restrict__ x, __half* __restrict__ xh,
    const float* __restrict__ ow1, const float* __restrict__ ow2,
    const float* __restrict__ dw1, const float* __restrict__ dw2,
    __half* __restrict__ w1h, __half* __restrict__ w2h,
    float* __restrict__ dw1T, float* __restrict__ dw2T)
{
    const int t = threadIdx.x;
    if (blockIdx.x < 224) {
        int h = blockIdx.x % H_, b = blockIdx.x / H_;
        __shared__ float s[64*W_];
        for (int i = t; i < 64*W_; i += 256) {
            int c = i / W_, w = i - c*W_;
            s[i] = x[((b*64 + c)*H_ + h)*W_ + w];
        }
        __syncthreads();
        size_t rb = (size_t)(b*H_ + h)*W_*64;
        for (int j = t; j < 32*W_; j += 256) {
            int w = j >> 5, cp = j & 31; int c0 = cp*2;
            float f0 = s[c0*W_ + w], f1 = s[(c0+1)*W_ + w];
            __half2 hp; hp.x = __float2half_rn(f0); hp.y = __float2half_rn(f1);
            *(__half2*)(xh + rb + w*64 + c0) = hp;
        }
        return;
    }
    const int N1 = 25*64*64;
    const int N2 = 49*112*64;
    const int N3 = 25*64;
    const int N4 = 49*64;
    int idx = (blockIdx.x - 224)*256 + t;
    if (idx < N1) {
        int ci = idx & 63; int r = idx >> 6; int co = r & 63; int tap = r >> 6;
        float v = (co < 50) ? ow1[(size_t)(co*64 + ci)*25 + tap] : 0.f;
        w1h[idx] = __float2half_rn(v);
    } else if (idx < N1 + N2) {
        int i = idx - N1;
        int ci = i & 63; int r = i >> 6; int co = r % 112; int tap = r / 112;
        float v = (co < 98) ? ow2[(size_t)(co*64 + ci)*49 + tap] : 0.f;
        w2h[i] = __float2half_rn(v);
    } else if (idx < N1 + N2 + N3) {
        int i = idx - N1 - N2;
        int kk = i >> 6, c = i & 63;
        dw1T[i] = dw1[c*25 + kk];
    } else if (idx < N1 + N2 + N3 + N4) {
        int i = idx - N1 - N2 - N3;
        int kk = i >> 6, c = i & 63;
        dw2T[i] = dw2[c*49 + kk];
    }
}

// ---------------------------------------------------------------------------
// Offset conv, implicit GEMM on tensor cores, single fp16 pass.
// M = 112 (2 rows x 56 px, NO m-padding) -> 7 warps x 1 m16-tile; 224 threads.
// Per-lane m -> (row, px) decode handles tiles straddling the row boundary.
// grid = (28, B, 2) = 224 blocks.
// ---------------------------------------------------------------------------
template<int K, int DIL, int PAD, int CO, int COP>
__global__ void __launch_bounds__(224) conv_mma_kernel(
    const __half* __restrict__ Ih,
    const __half* __restrict__ Wh,
    const float* __restrict__ bias, float* __restrict__ out)
{
    constexpr int KK  = K*K;
    constexpr int WE  = (K-1)*DIL + 56;   // extended row (halo + 56 px)
    constexpr int COH = COP/2;
    constexpr int NTn = COH/8;            // n-tiles of 8 per warp
    constexpr int AE  = WE*72;            // u16 elems per row plane
    constexpr int BE  = COH*72;           // u16 elems per B buffer

    extern __shared__ __align__(16) u16 sm[];
    u16* sA = sm;                         // 2 planes: row0, row1
    u16* sB = sm + 2*AE;                  // [buf] BE each

    const int t = threadIdx.x, lane = t & 31, wid = t >> 5;
    const int h0 = blockIdx.x*2, b = blockIdx.y;
    const int colbase = blockIdx.z * COH;
    const int kq   = (lane & 3)*2;
    const int qrow = lane >> 2;

    // m indices of this lane's two fragment rows (m16 tile wid)
    const int m0 = wid*16 + qrow;        // 0..111
    const int m1 = m0 + 8;
    const int r0 = (m0 >= 56) ? 1 : 0, px0 = m0 - 56*r0;
    const int r1 = (m1 >= 56) ? 1 : 0, px1 = m1 - 56*r1;
    const int abase0 = r0*AE + px0*72;
    const int abase1 = r1*AE + px1*72;

    const u32 smbase = (u32)__cvta_generic_to_shared(sm);
    const u32 dB = smbase + 2*AE*2;       // bytes

    float acc[NTn][4];
    #pragma unroll
    for (int nt = 0; nt < NTn; ++nt) {
        int co0 = colbase + nt*8 + kq;
        float b0 = (co0   < CO) ? bias[co0]   : 0.f;
        float b1 = (co0+1 < CO) ? bias[co0+1] : 0.f;
        acc[nt][0] = b0; acc[nt][1] = b1;
        acc[nt][2] = b0; acc[nt][3] = b1;
    }

    // prologue: stage B for tap 0 into buffer 0
    for (int c = t; c < COH*8; c += 224) {
        int co = c >> 3, kc = c & 7;
        cp16(dB + (u32)(co*72 + kc*8)*2, Wh + (size_t)(colbase + co)*64 + kc*8);
    }
    CP_COMMIT();

    for (int ky = 0; ky < K; ++ky) {
        const int hp = h0 + ky*DIL - PAD;    // input row for plane 0
        for (int c = t; c < 2*WE*8; c += 224) {
            int rr = c / (WE*8);
            int j  = (c >> 3) % WE;
            int kc = c & 7;
            int g = j - PAD, hh = hp + rr;
            u32 off = (u32)(rr*AE + j*72 + kc*8)*2;
            if ((unsigned)hh < (unsigned)H_ && (unsigned)g < (unsigned)W_) {
                cp16(smbase + off, Ih + ((size_t)(b*H_ + hh)*W_ + g)*64 + kc*8);
            } else {
                float4 z = make_float4(0.f,0.f,0.f,0.f);
                *(float4*)(sA + rr*AE + j*72 + kc*8) = z;
            }
        }
        CP_COMMIT();
        CP_WAIT0();
        __syncthreads();

        for (int kx = 0; kx < K; ++kx) {
            const int tap = ky*K + kx;
            if (tap + 1 < KK) {
                u32 dst = dB + (u32)((tap+1) & 1)*(BE*2);
                const __half* wh = Wh + (size_t)(tap+1)*COP*64;
                for (int c = t; c < COH*8; c += 224) {
                    int co = c >> 3, kc = c & 7;
                    cp16(dst + (u32)(co*72 + kc*8)*2,
                         wh + (size_t)(colbase + co)*64 + kc*8);
                }
                CP_COMMIT();
            }

            const u16* Bh = sB + (size_t)(tap & 1)*BE;
            const int kxo = kx*DIL*72;
            const u16* A0 = sA + abase0 + kxo;
            const u16* A1 = sA + abase1 + kxo;

            #pragma unroll
            for (int ks = 0; ks < 4; ++ks) {
                const int kk = ks*16 + kq;
                u32 xh0 = *(const u32*)(A0 + kk);
                u32 xh1 = *(const u32*)(A1 + kk);
                u32 xh2 = *(const u32*)(A0 + kk + 8);
                u32 xh3 = *(const u32*)(A1 + kk + 8);
                #pragma unroll
                for (int nt = 0; nt < NTn; ++nt) {
                    const int cb = (nt*8 + qrow)*72;
                    u32 bh0 = *(const u32*)(Bh + cb + kk);
                    u32 bh1 = *(const u32*)(Bh + cb + kk + 8);
                    mma_f16(acc[nt], xh0,xh1,xh2,xh3, bh0,bh1);
                }
            }
            CP_WAIT0();
            __syncthreads();
        }
    }

    // epilogue: every m < 112 is a valid pixel
    float* po0 = out + ((size_t)(b*H_ + h0 + r0)*W_ + px0)*CO;
    float* po1 = out + ((size_t)(b*H_ + h0 + r1)*W_ + px1)*CO;
    #pragma unroll
    for (int nt = 0; nt < NTn; ++nt) {
        int co0 = colbase + nt*8 + kq;
        if (co0   < CO) { po0[co0]   = acc[nt][0]; po1[co0]   = acc[nt][2]; }
        if (co0+1 < CO) { po0[co0+1] = acc[nt][1]; po1[co0+1] = acc[nt][3]; }
    }
}

// ---------------------------------------------------------------------------
// Deformable depthwise sampling, stage 1. Gathers from fp16 image (halved
// L1 wavefronts); bilinear/dw weights fp32. Emits fp16 output only.
// grid = (2 half-rows, H, B), 448 threads = 28 px x 16 channel-float4.
// ---------------------------------------------------------------------------
template<int K, int DIL, int PAD>
__global__ void __launch_bounds__(448) deform_sample_kernel(
    const __half* __restrict__ img, const float* __restrict__ off,
    const float* __restrict__ dwT, __half* __restrict__ oh)
{
    constexpr int KK = K*K;
    constexpr int NTASK = 28*KK;
    __shared__ __align__(16) float4 s_dw4[KK*16];
    __shared__ __align__(16) short4 s_idx[NTASK];
    __shared__ __align__(16) float4 s_wt [NTASK];

    const int t = threadIdx.x;
    const int half = blockIdx.x, h = blockIdx.y, b = blockIdx.z;
    const int w0 = half * 28;

    const float4* dwT4 = (const float4*)dwT;
    for (int i = t; i < KK*16; i += 448) s_dw4[i] = dwT4[i];

    const float2* ob2 = (const float2*)(off + ((size_t)(b*H_ + h)*W_ + w0)*2*KK);
    for (int i = t; i < NTASK; i += 448) {
        int wl = i / KK, kk = i - wl*KK;
        int ky = kk / K, kx = kk - ky*K;
        float2 d = ob2[i];
        float py = (float)(h + ky*DIL - PAD) + d.x;
        float px = (float)(w0 + wl + kx*DIL - PAD) + d.y;
        float y0f = floorf(py), x0f = floorf(px);
        float wy = py - y0f,    wx = px - x0f;
        int y0 = (int)y0f, x0i = (int)x0f;
        int y1 = y0 + 1,   x1  = x0i + 1;
        float vy0 = (y0  >= 0 && y0  < H_) ? 1.f : 0.f;
        float vy1 = (y1  >= 0 && y1  < H_) ? 1.f : 0.f;
        float vx0 = (x0i >= 0 && x0i < W_) ? 1.f : 0.f;
        float vx1 = (x1  >= 0 && x1  < W_) ? 1.f : 0.f;
        int y0c = min(max(y0, 0), H_-1), y1c = min(max(y1, 0), H_-1);
        int x0c = min(max(x0i,0), W_-1), x1c = min(max(x1, 0), W_-1);
        int r0 = y0c*W_, r1 = y1c*W_;
        s_idx[i] = make_short4((short)(r0+x0c), (short)(r0+x1c),
                               (short)(r1+x0c), (short)(r1+x1c));
        s_wt[i]  = make_float4((1.f-wy)*(1.f-wx)*vy0*vx0,
                               (1.f-wy)*wx      *vy0*vx1,
                               wy      *(1.f-wx)*vy1*vx0,
                               wy      *wx      *vy1*vx1);
    }
    __syncthreads();

    const int c4 = t & 15;
    const int wl = t >> 4;
    const int w  = w0 + wl;
    const uint2* imgb = (const uint2*)img + (size_t)b*HW_*16;

    float4 a = make_float4(0.f, 0.f, 0.f, 0.f);
    #pragma unroll 4
    for (int kk = 0; kk < KK; ++kk) {
        short4 id = s_idx[wl*KK + kk];
        float4 wt = s_wt [wl*KK + kk];
        float4 g00 = ld4h(imgb + (int)id.x*16 + c4);
        float4 g01 = ld4h(imgb + (int)id.y*16 + c4);
        float4 g10 = ld4h(imgb + (int)id.z*16 + c4);
        float4 g11 = ld4h(imgb + (int)id.w*16 + c4);
        float4 dv  = s_dw4[kk*16 + c4];
        float sx_ = g00.x*wt.x + g01.x*wt.y + g10.x*wt.z + g11.x*wt.w;
        float sy_ = g00.y*wt.x + g01.y*wt.y + g10.y*wt.z + g11.y*wt.w;
        float sz_ = g00.z*wt.x + g01.z*wt.y + g10.z*wt.z + g11.z*wt.w;
        float sw_ = g00.w*wt.x + g01.w*wt.y + g10.w*wt.z + g11.w*wt.w;
        a.x += sx_*dv.x; a.y += sy_*dv.y; a.z += sz_*dv.z; a.w += sw_*dv.w;
    }
    const size_t p = (size_t)(b*H_ + h)*W_ + w;
    __half2 hp0; hp0.x = __float2half_rn(a.x); hp0.y = __float2half_rn(a.y);
    __half2 hp1; hp1.x = __float2half_rn(a.z); hp1.y = __float2half_rn(a.w);
    __half2* ph = (__half2*)(oh + p*64 + c4*4);
    ph[0] = hp0; ph[1] = hp1;
}

// ---------------------------------------------------------------------------
// Stage-2 deform (fp16 gather) + fused 1x1 pointwise conv + x-multiply (NCHW).
// grid = (2 half-rows, H, B), 448 threads. Dynamic smem.
// ---------------------------------------------------------------------------
template<int K, int DIL, int PAD>
__global__ void __launch_bounds__(448) deform_pw_kernel(
    const __half* __restrict__ img,  // attn1 NHWC fp16
    const float* __restrict__ off,   // off2 NHWC
    const float* __restrict__ dwT,   // [kk][c]
    const float* __restrict__ pw,    // [64,64] (co,ci)
    const float* __restrict__ pb,    // [64]
    const float* __restrict__ x,     // original x, NCHW
    float* __restrict__ out)         // NCHW
{
    constexpr int KK = K*K;
    constexpr int NTASK = 28*KK;
    extern __shared__ __align__(16) char sraw[];
    float4* s_dw4 = (float4*)sraw;                               // KK*16*16 B
    char*   reg   = sraw + KK*16*16;
    short4* s_idx = (short4*)reg;                                // NTASK*8
    float4* s_wt  = (float4*)(reg + NTASK*8);                    // NTASK*16
    float*  s_attn= (float*) (reg + NTASK*24);                   // 28*64*4
    // overlay (valid after gather):
    float*  s_pwT = (float*)reg;                                 // 16384
    float*  s_pb  = (float*)(reg + 16384);                       // 256
    float*  s_out = (float*)(reg + 16640);                       // 28*64*4

    const int t = threadIdx.x;
    const int half = blockIdx.x, h = blockIdx.y, b = blockIdx.z;
    const int w0 = half * 28;

    const float4* dwT4 = (const float4*)dwT;
    for (int i = t; i < KK*16; i += 448) s_dw4[i] = dwT4[i];

    const float2* ob2 = (const float2*)(off + ((size_t)(b*H_ + h)*W_ + w0)*2*KK);
    for (int i = t; i < NTASK; i += 448) {
        int wl = i / KK, kk = i - wl*KK;
        int ky = kk / K, kx = kk - ky*K;
        float2 d = ob2[i];
        float py = (float)(h + ky*DIL - PAD) + d.x;
        float px = (float)(w0 + wl + kx*DIL - PAD) + d.y;
        float y0f = floorf(py), x0f = floorf(px);
        float wy = py - y0f,    wx = px - x0f;
        int y0 = (int)y0f, x0i = (int)x0f;
        int y1 = y0 + 1,   x1  = x0i + 1;
        float vy0 = (y0  >= 0 && y0  < H_) ? 1.f : 0.f;
        float vy1 = (y1  >= 0 && y1  < H_) ? 1.f : 0.f;
        float vx0 = (x0i >= 0 && x0i < W_) ? 1.f : 0.f;
        float vx1 = (x1  >= 0 && x1  < W_) ? 1.f : 0.f;
        int y0c = min(max(y0, 0), H_-1), y1c = min(max(y1, 0), H_-1);
        int x0c = min(max(x0i,0), W_-1), x1c = min(max(x1, 0), W_-1);
        int r0 = y0c*W_, r1 = y1c*W_;
        s_idx[i] = make_short4((short)(r0+x0c), (short)(r0+x1c),
                               (short)(r1+x0c), (short)(r1+x1c));
        s_wt[i]  = make_float4((1.f-wy)*(1.f-wx)*vy0*vx0,
                               (1.f-wy)*wx      *vy0*vx1,
                               wy      *(1.f-wx)*vy1*vx0,
                               wy      *wx      *vy1*vx1);
    }
    __syncthreads();

    const int c4 = t & 15;
    const int wl = t >> 4;
    const uint2* imgb = (const uint2*)img + (size_t)b*HW_*16;

    float4 a = make_float4(0.f, 0.f, 0.f, 0.f);
    #pragma unroll 4
    for (int kk = 0; kk < KK; ++kk) {
        short4 id = s_idx[wl*KK + kk];
        float4 wt = s_wt [wl*KK + kk];
        float4 g00 = ld4h(imgb + (int)id.x*16 + c4);
        float4 g01 = ld4h(imgb + (int)id.y*16 + c4);
        float4 g10 = ld4h(imgb + (int)id.z*16 + c4);
        float4 g11 = ld4h(imgb + (int)id.w*16 + c4);
        float4 dv  = s_dw4[kk*16 + c4];
        float sx_ = g00.x*wt.x + g01.x*wt.y + g10.x*wt.z + g11.x*wt.w;
        float sy_ = g00.y*wt.x + g01.y*wt.y + g10.y*wt.z + g11.y*wt.w;
        float sz_ = g00.z*wt.x + g01.z*wt.y + g10.z*wt.z + g11.z*wt.w;
        float sw_ = g00.w*wt.x + g01.w*wt.y + g10.w*wt.z + g11.w*wt.w;
        a.x += sx_*dv.x; a.y += sy_*dv.y; a.z += sz_*dv.z; a.w += sw_*dv.w;
    }
    ((float4*)s_attn)[wl*16 + c4] = a;
    __syncthreads();                         // gather done; idx/wt now dead

    for (int i = t; i < 4096; i += 448) {
        int co = i >> 6, ci = i & 63;
        s_pwT[ci*64 + co] = pw[i];
    }
    if (t < 64) s_pb[t] = pb[t];
    __syncthreads();

    const int co0 = c4*4;
    float4 accp = make_float4(0.f, 0.f, 0.f, 0.f);
    const float* ar = s_attn + wl*64;
    #pragma unroll 8
    for (int ci = 0; ci < 64; ++ci) {
        float av = ar[ci];
        float4 wv = ((const float4*)(s_pwT + ci*64))[c4];
        accp.x += av*wv.x; accp.y += av*wv.y;
        accp.z += av*wv.z; accp.w += av*wv.w;
    }
    s_out[(co0  )*28 + wl] = accp.x + s_pb[co0];
    s_out[(co0+1)*28 + wl] = accp.y + s_pb[co0+1];
    s_out[(co0+2)*28 + wl] = accp.z + s_pb[co0+2];
    s_out[(co0+3)*28 + wl] = accp.w + s_pb[co0+3];
    __syncthreads();

    for (int i = t; i < 64*28; i += 448) {
        int c = i / 28, wl2 = i - c*28;
        size_t idx = ((size_t)(b*64 + c)*H_ + h)*W_ + w0 + wl2;
        out[idx] = x[idx] * s_out[c*28 + wl2];
    }
}

// ---------------------------------------------------------------------------
extern "C" void kernel_launch(void* const* d_in, const int* in_sizes, int n_in,
                              void* d_out, int out_size)
{
    const float* x   = (const float*)d_in[0];
    const float* ow1 = (const float*)d_in[1];
    const float* ob1 = (const float*)d_in[2];
    const float* dw1 = (const float*)d_in[3];
    const float* ow2 = (const float*)d_in[4];
    const float* ob2 = (const float*)d_in[5];
    const float* dw2 = (const float*)d_in[6];
    const float* pww = (const float*)d_in[7];
    const float* pwb = (const float*)d_in[8];
    float* out = (float*)d_out;

    float *off1, *off2, *dw1T, *dw2T;
    __half *xh, *a1h, *w1h, *w2h;
    cudaGetSymbolAddress((void**)&xh,    g_xh);
    cudaGetSymbolAddress((void**)&off1,  g_off1);
    cudaGetSymbolAddress((void**)&a1h,   g_a1h);
    cudaGetSymbolAddress((void**)&off2,  g_off2);
    cudaGetSymbolAddress((void**)&w1h,   g_w1h);
    cudaGetSymbolAddress((void**)&w2h,   g_w2h);
    cudaGetSymbolAddress((void**)&dw1T,  g_dw1T);
    cudaGetSymbolAddress((void**)&dw2T,  g_dw2T);

    // conv smem: 2 A planes + 2 B buffers (bytes); WE = (K-1)*DIL + 56
    const int SMEM1 = 2*(60*72)*2 + 2*(32*72)*2;    // 26496
    const int SMEM2 = 2*(74*72)*2 + 2*(56*72)*2;    // 37440
    const int SMEMD = 49*16*16 + 28*49*24 + 28*64*4; // 52640
    cudaFuncSetAttribute(conv_mma_kernel<5,1,2,50,64>,
        cudaFuncAttributeMaxDynamicSharedMemorySize, SMEM1);
    cudaFuncSetAttribute(conv_mma_kernel<7,3,9,98,112>,
        cudaFuncAttributeMaxDynamicSharedMemorySize, SMEM2);
    cudaFuncSetAttribute(deform_pw_kernel<7,3,9>,
        cudaFuncAttributeMaxDynamicSharedMemorySize, SMEMD);

    // fused prelude: 224 transpose blocks + weight-prep blocks
    prelude_kernel<<<224 + PREP_BLOCKS, 256>>>(
        x, xh, ow1, ow2, dw1, dw2, w1h, w2h, dw1T, dw2T);

    // stage 1: K=5, dil=1, pad=2, CO=50 (pad 64)
    conv_mma_kernel<5,1,2,50,64><<<dim3(28, B_, 2), 224, SMEM1>>>(
        xh, w1h, ob1, off1);
    deform_sample_kernel<5,1,2><<<dim3(2, H_, B_), 448>>>(
        xh, off1, dw1T, a1h);

    // stage 2: K=7, dil=3, pad=9, CO=98 (pad 112)
    conv_mma_kernel<7,3,9,98,112><<<dim3(28, B_, 2), 224, SMEM2>>>(
        a1h, w2h, ob2, off2);

    // deform2 + pointwise + x-multiply, fused
    deform_pw_kernel<7,3,9><<<dim3(2, H_, B_), 448, SMEMD>>>(
        a1h, off2, dw2T, pww, pwb, x, out);
}

// round 17
// speedup vs baseline: 1.1466x; 1.0294x over previous
#include <cuda_runtime.h>
#include <cuda_fp16.h>

#define B_ 4
#define H_ 56
#define W_ 56
#define HW_ (H_*W_)

typedef unsigned int  u32;
typedef unsigned short u16;

// ---------------------------------------------------------------------------
// Scratch (device globals; no allocation allowed)
// ---------------------------------------------------------------------------
__device__ __align__(16) __half g_xh [B_*HW_*64];
__device__ __align__(16) float g_off1 [B_*HW_*50];
__device__ __align__(16) __half g_a1h[B_*HW_*64];
__device__ __align__(16) float g_off2 [B_*HW_*98];
// fp16 weights: [tap][co(COP)][ci(64)]
__device__ __align__(16) __half g_w1h[25*64*64];
__device__ __align__(16) __half g_w2h[49*128*64];   // co padded to 128
__device__ __align__(16) float g_dw1T [25*64];   // [kk][c]
__device__ __align__(16) float g_dw2T [49*64];

// ---------------------------------------------------------------------------
// helpers
// ---------------------------------------------------------------------------
__device__ __forceinline__ void cp16(u32 dst, const void* src){
    asm volatile("cp.async.cg.shared.global [%0], [%1], 16;" :: "r"(dst), "l"(src));
}
#define CP_COMMIT() asm volatile("cp.async.commit_group;")
#define CP_WAIT0()  asm volatile("cp.async.wait_group 0;")
__device__ __forceinline__ void mma_f16(float* d, u32 a0,u32 a1,u32 a2,u32 a3,u32 b0,u32 b1){
    asm volatile("mma.sync.aligned.m16n8k16.row.col.f32.f16.f16.f32 "
      "{%0,%1,%2,%3}, {%4,%5,%6,%7}, {%8,%9}, {%0,%1,%2,%3};"
      : "+f"(d[0]),"+f"(d[1]),"+f"(d[2]),"+f"(d[3])
      : "r"(a0),"r"(a1),"r"(a2),"r"(a3),"r"(b0),"r"(b1));
}
// load 4 channels stored as fp16 (8 bytes) and widen to float4
__device__ __forceinline__ float4 ld4h(const uint2* p){
    uint2 q = *p;
    __half2 h0 = *reinterpret_cast<__half2*>(&q.x);
    __half2 h1 = *reinterpret_cast<__half2*>(&q.y);
    float2 f0 = __half22float2(h0), f1 = __half22float2(h1);
    return make_float4(f0.x, f0.y, f1.x, f1.y);
}

// ---------------------------------------------------------------------------
// Fused prelude: transpose blocks [0, 224) + weight-prep blocks [224, ...)
// ---------------------------------------------------------------------------
#define NPREP_ (25*64*64 + 49*128*64 + 25*64 + 49*64)
#define PREP_BLOCKS ((NPREP_ + 255)/256)

__global__ void __launch_bounds__(256) prelude_kernel(
    const float* __restrict__ x, __half* __restrict__ xh,
    const float* __restrict__ ow1, const float* __restrict__ ow2,
    const float* __restrict__ dw1, const float* __restrict__ dw2,
    __half* __restrict__ w1h, __half* __restrict__ w2h,
    float* __restrict__ dw1T, float* __restrict__ dw2T)
{
    const int t = threadIdx.x;
    if (blockIdx.x < 224) {
        int h = blockIdx.x % H_, b = blockIdx.x / H_;
        __shared__ float s[64*W_];
        for (int i = t; i < 64*W_; i += 256) {
            int c = i / W_, w = i - c*W_;
            s[i] = x[((b*64 + c)*H_ + h)*W_ + w];
        }
        __syncthreads();
        size_t rb = (size_t)(b*H_ + h)*W_*64;
        for (int j = t; j < 32*W_; j += 256) {
            int w = j >> 5, cp = j & 31; int c0 = cp*2;
            float f0 = s[c0*W_ + w], f1 = s[(c0+1)*W_ + w];
            __half2 hp; hp.x = __float2half_rn(f0); hp.y = __float2half_rn(f1);
            *(__half2*)(xh + rb + w*64 + c0) = hp;
        }
        return;
    }
    const int N1 = 25*64*64;
    const int N2 = 49*128*64;
    const int N3 = 25*64;
    const int N4 = 49*64;
    int idx = (blockIdx.x - 224)*256 + t;
    if (idx < N1) {
        int ci = idx & 63; int r = idx >> 6; int co = r & 63; int tap = r >> 6;
        float v = (co < 50) ? ow1[(size_t)(co*64 + ci)*25 + tap] : 0.f;
        w1h[idx] = __float2half_rn(v);
    } else if (idx < N1 + N2) {
        int i = idx - N1;
        int ci = i & 63; int r = i >> 6; int co = r & 127; int tap = r >> 7;
        float v = (co < 98) ? ow2[(size_t)(co*64 + ci)*49 + tap] : 0.f;
        w2h[i] = __float2half_rn(v);
    } else if (idx < N1 + N2 + N3) {
        int i = idx - N1 - N2;
        int kk = i >> 6, c = i & 63;
        dw1T[i] = dw1[c*25 + kk];
    } else if (idx < N1 + N2 + N3 + N4) {
        int i = idx - N1 - N2 - N3;
        int kk = i >> 6, c = i & 63;
        dw2T[i] = dw2[c*49 + kk];
    }
}

// ---------------------------------------------------------------------------
// Offset conv, implicit GEMM on tensor cores, single fp16 pass.
// M = 112 (2 rows x 56 px, no m-padding) -> 7 warps x 1 m16-tile; 224 threads.
// Co split into CBLK-wide blocks -> grid (28, B, COP/CBLK) = 448 blocks
// (~3 blocks/SM, ~21 warps/SM) for latency hiding.
// ---------------------------------------------------------------------------
template<int K, int DIL, int PAD, int CO, int COP, int CBLK>
__global__ void __launch_bounds__(224) conv_mma_kernel(
    const __half* __restrict__ Ih,
    const __half* __restrict__ Wh,
    const float* __restrict__ bias, float* __restrict__ out)
{
    constexpr int KK  = K*K;
    constexpr int WE  = (K-1)*DIL + 56;   // extended row (halo + 56 px)
    constexpr int NTn = CBLK/8;           // n-tiles of 8 per warp
    constexpr int AE  = WE*72;            // u16 elems per row plane
    constexpr int BE  = CBLK*72;          // u16 elems per B buffer

    extern __shared__ __align__(16) u16 sm[];
    u16* sA = sm;                         // 2 planes: row0, row1
    u16* sB = sm + 2*AE;                  // [buf] BE each

    const int t = threadIdx.x, lane = t & 31, wid = t >> 5;
    const int h0 = blockIdx.x*2, b = blockIdx.y;
    const int colbase = blockIdx.z * CBLK;
    const int kq   = (lane & 3)*2;
    const int qrow = lane >> 2;

    // m indices of this lane's two fragment rows (m16 tile wid)
    const int m0 = wid*16 + qrow;        // 0..111
    const int m1 = m0 + 8;
    const int r0 = (m0 >= 56) ? 1 : 0, px0 = m0 - 56*r0;
    const int r1 = (m1 >= 56) ? 1 : 0, px1 = m1 - 56*r1;
    const int abase0 = r0*AE + px0*72;
    const int abase1 = r1*AE + px1*72;

    const u32 smbase = (u32)__cvta_generic_to_shared(sm);
    const u32 dB = smbase + 2*AE*2;       // bytes

    float acc[NTn][4];
    #pragma unroll
    for (int nt = 0; nt < NTn; ++nt) {
        int co0 = colbase + nt*8 + kq;
        float b0 = (co0   < CO) ? bias[co0]   : 0.f;
        float b1 = (co0+1 < CO) ? bias[co0+1] : 0.f;
        acc[nt][0] = b0; acc[nt][1] = b1;
        acc[nt][2] = b0; acc[nt][3] = b1;
    }

    // prologue: stage B for tap 0 into buffer 0
    for (int c = t; c < CBLK*8; c += 224) {
        int co = c >> 3, kc = c & 7;
        cp16(dB + (u32)(co*72 + kc*8)*2, Wh + (size_t)(colbase + co)*64 + kc*8);
    }
    CP_COMMIT();

    for (int ky = 0; ky < K; ++ky) {
        const int hp = h0 + ky*DIL - PAD;    // input row for plane 0
        for (int c = t; c < 2*WE*8; c += 224) {
            int rr = c / (WE*8);
            int j  = (c >> 3) % WE;
            int kc = c & 7;
            int g = j - PAD, hh = hp + rr;
            u32 off = (u32)(rr*AE + j*72 + kc*8)*2;
            if ((unsigned)hh < (unsigned)H_ && (unsigned)g < (unsigned)W_) {
                cp16(smbase + off, Ih + ((size_t)(b*H_ + hh)*W_ + g)*64 + kc*8);
            } else {
                float4 z = make_float4(0.f,0.f,0.f,0.f);
                *(float4*)(sA + rr*AE + j*72 + kc*8) = z;
            }
        }
        CP_COMMIT();
        CP_WAIT0();
        __syncthreads();

        for (int kx = 0; kx < K; ++kx) {
            const int tap = ky*K + kx;
            if (tap + 1 < KK) {
                u32 dst = dB + (u32)((tap+1) & 1)*(BE*2);
                const __half* wh = Wh + (size_t)(tap+1)*COP*64;
                for (int c = t; c < CBLK*8; c += 224) {
                    int co = c >> 3, kc = c & 7;
                    cp16(dst + (u32)(co*72 + kc*8)*2,
                         wh + (size_t)(colbase + co)*64 + kc*8);
                }
                CP_COMMIT();
            }

            const u16* Bh = sB + (size_t)(tap & 1)*BE;
            const int kxo = kx*DIL*72;
            const u16* A0 = sA + abase0 + kxo;
            const u16* A1 = sA + abase1 + kxo;

            #pragma unroll
            for (int ks = 0; ks < 4; ++ks) {
                const int kk = ks*16 + kq;
                u32 xh0 = *(const u32*)(A0 + kk);
                u32 xh1 = *(const u32*)(A1 + kk);
                u32 xh2 = *(const u32*)(A0 + kk + 8);
                u32 xh3 = *(const u32*)(A1 + kk + 8);
                #pragma unroll
                for (int nt = 0; nt < NTn; ++nt) {
                    const int cb = (nt*8 + qrow)*72;
                    u32 bh0 = *(const u32*)(Bh + cb + kk);
                    u32 bh1 = *(const u32*)(Bh + cb + kk + 8);
                    mma_f16(acc[nt], xh0,xh1,xh2,xh3, bh0,bh1);
                }
            }
            CP_WAIT0();
            __syncthreads();
        }
    }

    // epilogue: every m < 112 is a valid pixel
    float* po0 = out + ((size_t)(b*H_ + h0 + r0)*W_ + px0)*CO;
    float* po1 = out + ((size_t)(b*H_ + h0 + r1)*W_ + px1)*CO;
    #pragma unroll
    for (int nt = 0; nt < NTn; ++nt) {
        int co0 = colbase + nt*8 + kq;
        if (co0   < CO) { po0[co0]   = acc[nt][0]; po1[co0]   = acc[nt][2]; }
        if (co0+1 < CO) { po0[co0+1] = acc[nt][1]; po1[co0+1] = acc[nt][3]; }
    }
}

// ---------------------------------------------------------------------------
// Deformable depthwise sampling, stage 1 (fp16 gathers, fp16 output).
// grid = (2 half-rows, H, B), 448 threads = 28 px x 16 channel-float4.
// ---------------------------------------------------------------------------
template<int K, int DIL, int PAD>
__global__ void __launch_bounds__(448) deform_sample_kernel(
    const __half* __restrict__ img, const float* __restrict__ off,
    const float* __restrict__ dwT, __half* __restrict__ oh)
{
    constexpr int KK = K*K;
    constexpr int NTASK = 28*KK;
    __shared__ __align__(16) float4 s_dw4[KK*16];
    __shared__ __align__(16) short4 s_idx[NTASK];
    __shared__ __align__(16) float4 s_wt [NTASK];

    const int t = threadIdx.x;
    const int half = blockIdx.x, h = blockIdx.y, b = blockIdx.z;
    const int w0 = half * 28;

    const float4* dwT4 = (const float4*)dwT;
    for (int i = t; i < KK*16; i += 448) s_dw4[i] = dwT4[i];

    const float2* ob2 = (const float2*)(off + ((size_t)(b*H_ + h)*W_ + w0)*2*KK);
    for (int i = t; i < NTASK; i += 448) {
        int wl = i / KK, kk = i - wl*KK;
        int ky = kk / K, kx = kk - ky*K;
        float2 d = ob2[i];
        float py = (float)(h + ky*DIL - PAD) + d.x;
        float px = (float)(w0 + wl + kx*DIL - PAD) + d.y;
        float y0f = floorf(py), x0f = floorf(px);
        float wy = py - y0f,    wx = px - x0f;
        int y0 = (int)y0f, x0i = (int)x0f;
        int y1 = y0 + 1,   x1  = x0i + 1;
        float vy0 = (y0  >= 0 && y0  < H_) ? 1.f : 0.f;
        float vy1 = (y1  >= 0 && y1  < H_) ? 1.f : 0.f;
        float vx0 = (x0i >= 0 && x0i < W_) ? 1.f : 0.f;
        float vx1 = (x1  >= 0 && x1  < W_) ? 1.f : 0.f;
        int y0c = min(max(y0, 0), H_-1), y1c = min(max(y1, 0), H_-1);
        int x0c = min(max(x0i,0), W_-1), x1c = min(max(x1, 0), W_-1);
        int r0 = y0c*W_, r1 = y1c*W_;
        s_idx[i] = make_short4((short)(r0+x0c), (short)(r0+x1c),
                               (short)(r1+x0c), (short)(r1+x1c));
        s_wt[i]  = make_float4((1.f-wy)*(1.f-wx)*vy0*vx0,
                               (1.f-wy)*wx      *vy0*vx1,
                               wy      *(1.f-wx)*vy1*vx0,
                               wy      *wx      *vy1*vx1);
    }
    __syncthreads();

    const int c4 = t & 15;
    const int wl = t >> 4;
    const int w  = w0 + wl;
    const uint2* imgb = (const uint2*)img + (size_t)b*HW_*16;

    float4 a = make_float4(0.f, 0.f, 0.f, 0.f);
    #pragma unroll 4
    for (int kk = 0; kk < KK; ++kk) {
        short4 id = s_idx[wl*KK + kk];
        float4 wt = s_wt [wl*KK + kk];
        float4 g00 = ld4h(imgb + (int)id.x*16 + c4);
        float4 g01 = ld4h(imgb + (int)id.y*16 + c4);
        float4 g10 = ld4h(imgb + (int)id.z*16 + c4);
        float4 g11 = ld4h(imgb + (int)id.w*16 + c4);
        float4 dv  = s_dw4[kk*16 + c4];
        float sx_ = g00.x*wt.x + g01.x*wt.y + g10.x*wt.z + g11.x*wt.w;
        float sy_ = g00.y*wt.x + g01.y*wt.y + g10.y*wt.z + g11.y*wt.w;
        float sz_ = g00.z*wt.x + g01.z*wt.y + g10.z*wt.z + g11.z*wt.w;
        float sw_ = g00.w*wt.x + g01.w*wt.y + g10.w*wt.z + g11.w*wt.w;
        a.x += sx_*dv.x; a.y += sy_*dv.y; a.z += sz_*dv.z; a.w += sw_*dv.w;
    }
    const size_t p = (size_t)(b*H_ + h)*W_ + w;
    __half2 hp0; hp0.x = __float2half_rn(a.x); hp0.y = __float2half_rn(a.y);
    __half2 hp1; hp1.x = __float2half_rn(a.z); hp1.y = __float2half_rn(a.w);
    __half2* ph = (__half2*)(oh + p*64 + c4*4);
    ph[0] = hp0; ph[1] = hp1;
}

// ---------------------------------------------------------------------------
// Stage-2 deform (fp16 gather) + fused 1x1 pointwise conv + x-multiply (NCHW).
// grid = (2 half-rows, H, B), 448 threads. Dynamic smem.
// ---------------------------------------------------------------------------
template<int K, int DIL, int PAD>
__global__ void __launch_bounds__(448) deform_pw_kernel(
    const __half* __restrict__ img,  // attn1 NHWC fp16
    const float* __restrict__ off,   // off2 NHWC
    const float* __restrict__ dwT,   // [kk][c]
    const float* __restrict__ pw,    // [64,64] (co,ci)
    const float* __restrict__ pb,    // [64]
    const float* __restrict__ x,     // original x, NCHW
    float* __restrict__ out)         // NCHW
{
    constexpr int KK = K*K;
    constexpr int NTASK = 28*KK;
    extern __shared__ __align__(16) char sraw[];
    float4* s_dw4 = (float4*)sraw;                               // KK*16*16 B
    char*   reg   = sraw + KK*16*16;
    short4* s_idx = (short4*)reg;                                // NTASK*8
    float4* s_wt  = (float4*)(reg + NTASK*8);                    // NTASK*16
    float*  s_attn= (float*) (reg + NTASK*24);                   // 28*64*4
    // overlay (valid after gather):
    float*  s_pwT = (float*)reg;                                 // 16384
    float*  s_pb  = (float*)(reg + 16384);                       // 256
    float*  s_out = (float*)(reg + 16640);                       // 28*64*4

    const int t = threadIdx.x;
    const int half = blockIdx.x, h = blockIdx.y, b = blockIdx.z;
    const int w0 = half * 28;

    const float4* dwT4 = (const float4*)dwT;
    for (int i = t; i < KK*16; i += 448) s_dw4[i] = dwT4[i];

    const float2* ob2 = (const float2*)(off + ((size_t)(b*H_ + h)*W_ + w0)*2*KK);
    for (int i = t; i < NTASK; i += 448) {
        int wl = i / KK, kk = i - wl*KK;
        int ky = kk / K, kx = kk - ky*K;
        float2 d = ob2[i];
        float py = (float)(h + ky*DIL - PAD) + d.x;
        float px = (float)(w0 + wl + kx*DIL - PAD) + d.y;
        float y0f = floorf(py), x0f = floorf(px);
        float wy = py - y0f,    wx = px - x0f;
        int y0 = (int)y0f, x0i = (int)x0f;
        int y1 = y0 + 1,   x1  = x0i + 1;
        float vy0 = (y0  >= 0 && y0  < H_) ? 1.f : 0.f;
        float vy1 = (y1  >= 0 && y1  < H_) ? 1.f : 0.f;
        float vx0 = (x0i >= 0 && x0i < W_) ? 1.f : 0.f;
        float vx1 = (x1  >= 0 && x1  < W_) ? 1.f : 0.f;
        int y0c = min(max(y0, 0), H_-1), y1c = min(max(y1, 0), H_-1);
        int x0c = min(max(x0i,0), W_-1), x1c = min(max(x1, 0), W_-1);
        int r0 = y0c*W_, r1 = y1c*W_;
        s_idx[i] = make_short4((short)(r0+x0c), (short)(r0+x1c),
                               (short)(r1+x0c), (short)(r1+x1c));
        s_wt[i]  = make_float4((1.f-wy)*(1.f-wx)*vy0*vx0,
                               (1.f-wy)*wx      *vy0*vx1,
                               wy      *(1.f-wx)*vy1*vx0,
                               wy      *wx      *vy1*vx1);
    }
    __syncthreads();

    const int c4 = t & 15;
    const int wl = t >> 4;
    const uint2* imgb = (const uint2*)img + (size_t)b*HW_*16;

    float4 a = make_float4(0.f, 0.f, 0.f, 0.f);
    #pragma unroll 4
    for (int kk = 0; kk < KK; ++kk) {
        short4 id = s_idx[wl*KK + kk];
        float4 wt = s_wt [wl*KK + kk];
        float4 g00 = ld4h(imgb + (int)id.x*16 + c4);
        float4 g01 = ld4h(imgb + (int)id.y*16 + c4);
        float4 g10 = ld4h(imgb + (int)id.z*16 + c4);
        float4 g11 = ld4h(imgb + (int)id.w*16 + c4);
        float4 dv  = s_dw4[kk*16 + c4];
        float sx_ = g00.x*wt.x + g01.x*wt.y + g10.x*wt.z + g11.x*wt.w;
        float sy_ = g00.y*wt.x + g01.y*wt.y + g10.y*wt.z + g11.y*wt.w;
        float sz_ = g00.z*wt.x + g01.z*wt.y + g10.z*wt.z + g11.z*wt.w;
        float sw_ = g00.w*wt.x + g01.w*wt.y + g10.w*wt.z + g11.w*wt.w;
        a.x += sx_*dv.x; a.y += sy_*dv.y; a.z += sz_*dv.z; a.w += sw_*dv.w;
    }
    ((float4*)s_attn)[wl*16 + c4] = a;
    __syncthreads();                         // gather done; idx/wt now dead

    for (int i = t; i < 4096; i += 448) {
        int co = i >> 6, ci = i & 63;
        s_pwT[ci*64 + co] = pw[i];
    }
    if (t < 64) s_pb[t] = pb[t];
    __syncthreads();

    const int co0 = c4*4;
    float4 accp = make_float4(0.f, 0.f, 0.f, 0.f);
    const float* ar = s_attn + wl*64;
    #pragma unroll 8
    for (int ci = 0; ci < 64; ++ci) {
        float av = ar[ci];
        float4 wv = ((const float4*)(s_pwT + ci*64))[c4];
        accp.x += av*wv.x; accp.y += av*wv.y;
        accp.z += av*wv.z; accp.w += av*wv.w;
    }
    s_out[(co0  )*28 + wl] = accp.x + s_pb[co0];
    s_out[(co0+1)*28 + wl] = accp.y + s_pb[co0+1];
    s_out[(co0+2)*28 + wl] = accp.z + s_pb[co0+2];
    s_out[(co0+3)*28 + wl] = accp.w + s_pb[co0+3];
    __syncthreads();

    for (int i = t; i < 64*28; i += 448) {
        int c = i / 28, wl2 = i - c*28;
        size_t idx = ((size_t)(b*64 + c)*H_ + h)*W_ + w0 + wl2;
        out[idx] = x[idx] * s_out[c*28 + wl2];
    }
}

// ---------------------------------------------------------------------------
extern "C" void kernel_launch(void* const* d_in, const int* in_sizes, int n_in,
                              void* d_out, int out_size)
{
    const float* x   = (const float*)d_in[0];
    const float* ow1 = (const float*)d_in[1];
    const float* ob1 = (const float*)d_in[2];
    const float* dw1 = (const float*)d_in[3];
    const float* ow2 = (const float*)d_in[4];
    const float* ob2 = (const float*)d_in[5];
    const float* dw2 = (const float*)d_in[6];
    const float* pww = (const float*)d_in[7];
    const float* pwb = (const float*)d_in[8];
    float* out = (float*)d_out;

    float *off1, *off2, *dw1T, *dw2T;
    __half *xh, *a1h, *w1h, *w2h;
    cudaGetSymbolAddress((void**)&xh,    g_xh);
    cudaGetSymbolAddress((void**)&off1,  g_off1);
    cudaGetSymbolAddress((void**)&a1h,   g_a1h);
    cudaGetSymbolAddress((void**)&off2,  g_off2);
    cudaGetSymbolAddress((void**)&w1h,   g_w1h);
    cudaGetSymbolAddress((void**)&w2h,   g_w2h);
    cudaGetSymbolAddress((void**)&dw1T,  g_dw1T);
    cudaGetSymbolAddress((void**)&dw2T,  g_dw2T);

    // conv smem: 2 A planes + 2 B buffers (bytes); WE = (K-1)*DIL + 56
    const int SMEM1 = 2*(60*72)*2 + 2*(16*72)*2;    // 21888
    const int SMEM2 = 2*(74*72)*2 + 2*(32*72)*2;    // 30528
    const int SMEMD = 49*16*16 + 28*49*24 + 28*64*4; // 52640
    cudaFuncSetAttribute(conv_mma_kernel<5,1,2,50,64,16>,
        cudaFuncAttributeMaxDynamicSharedMemorySize, SMEM1);
    cudaFuncSetAttribute(conv_mma_kernel<7,3,9,98,128,32>,
        cudaFuncAttributeMaxDynamicSharedMemorySize, SMEM2);
    cudaFuncSetAttribute(deform_pw_kernel<7,3,9>,
        cudaFuncAttributeMaxDynamicSharedMemorySize, SMEMD);

    // fused prelude: 224 transpose blocks + weight-prep blocks
    prelude_kernel<<<224 + PREP_BLOCKS, 256>>>(
        x, xh, ow1, ow2, dw1, dw2, w1h, w2h, dw1T, dw2T);

    // stage 1: K=5, dil=1, pad=2, CO=50 (pad 64, 4 co-blocks of 16)
    conv_mma_kernel<5,1,2,50,64,16><<<dim3(28, B_, 4), 224, SMEM1>>>(
        xh, w1h, ob1, off1);
    deform_sample_kernel<5,1,2><<<dim3(2, H_, B_), 448>>>(
        xh, off1, dw1T, a1h);

    // stage 2: K=7, dil=3, pad=9, CO=98 (pad 128, 4 co-blocks of 32)
    conv_mma_kernel<7,3,9,98,128,32><<<dim3(28, B_, 4), 224, SMEM2>>>(
        a1h, w2h, ob2, off2);

    // deform2 + pointwise + x-multiply, fused
    deform_pw_kernel<7,3,9><<<dim3(2, H_, B_), 448, SMEMD>>>(
        a1h, off2, dw2T, pww, pwb, x, out);
}